// round 1
// baseline (speedup 1.0000x reference)
#include <cuda_runtime.h>

#define BATCH 128

__device__ float g_partials[BATCH];

__device__ __forceinline__ float warp_sum(float v) {
#pragma unroll
    for (int o = 16; o; o >>= 1) v += __shfl_down_sync(0xffffffffu, v, o);
    return v;
}

// One block per batch element. 256 threads.
__global__ __launch_bounds__(256, 1)
void loss_main(const float* __restrict__ input,
               const float* __restrict__ target,
               const float* __restrict__ normals,
               const float* __restrict__ param_mean,
               const float* __restrict__ param_std,
               const float* __restrict__ u,
               const float* __restrict__ w_shp,
               const float* __restrict__ w_exp,
               const int*   __restrict__ keyindex,
               const int*   __restrict__ ridx_w,
               const int*   __restrict__ ridx_v)
{
    const int n    = blockIdx.x;
    const int tid  = threadIdx.x;
    const int lane = tid & 31;
    const int wid  = tid >> 5;

    __shared__ float sp[62], spg[62];          // denormalized params
    __shared__ float bv[600], bvg[600];        // base verts on kmix_v (pred / gt)
    __shared__ float colsq_w[8][50];           // per-warp partial column sq-sums
    __shared__ float tn_w[8][3];               // per-warp partial tmpv sq-sums
    __shared__ float wcol[50];                 // column norms of w_cat (kmix_w rows)
    __shared__ float tnsq[3];                  // tmpv row sq-norms
    __shared__ float vt[200][3], vtg[200][3];  // rotated verts (kmix_v points)
    __shared__ float red[256];                 // reduction scratch

    // ---- 0. denormalize params ----
    if (tid < 62) {
        float st = param_std[tid], mn = param_mean[tid];
        sp[tid]  = input [n * 62 + tid] * st + mn;
        spg[tid] = target[n * 62 + tid] * st + mn;
    }
    __syncthreads();

    // ---- 1. kmix_w pass: base verts (pred only) -> tmpv norms; fused column sq-norms ----
    float csq[50];
#pragma unroll
    for (int k = 0; k < 50; k++) csq[k] = 0.f;
    float tn0 = 0.f, tn1 = 0.f, tn2 = 0.f;

    for (int l = tid; l < 600; l += 256) {
        int j = l / 3, c = l - 3 * j;
        int vid = (j < 68) ? keyindex[j] : ridx_w[j - 68];
        int r = 3 * vid + c;
        float s = u[r];
        const float4* w4 = (const float4*)(w_shp + (size_t)r * 40);
#pragma unroll
        for (int q = 0; q < 10; q++) {
            float4 v = w4[q];
            s += v.x * sp[12 + 4 * q] + v.y * sp[13 + 4 * q]
               + v.z * sp[14 + 4 * q] + v.w * sp[15 + 4 * q];
            csq[4 * q + 0] += v.x * v.x;
            csq[4 * q + 1] += v.y * v.y;
            csq[4 * q + 2] += v.z * v.z;
            csq[4 * q + 3] += v.w * v.w;
        }
        const float2* e2 = (const float2*)(w_exp + (size_t)r * 10);
#pragma unroll
        for (int q = 0; q < 5; q++) {
            float2 v = e2[q];
            s += v.x * sp[52 + 2 * q] + v.y * sp[53 + 2 * q];
            csq[40 + 2 * q] += v.x * v.x;
            csq[41 + 2 * q] += v.y * v.y;
        }
        float s2 = s * s;
        if (c == 0) tn0 += s2; else if (c == 1) tn1 += s2; else tn2 += s2;
    }
    tn0 = warp_sum(tn0); tn1 = warp_sum(tn1); tn2 = warp_sum(tn2);
    if (lane == 0) { tn_w[wid][0] = tn0; tn_w[wid][1] = tn1; tn_w[wid][2] = tn2; }
#pragma unroll
    for (int k = 0; k < 50; k++) {
        float v = warp_sum(csq[k]);
        if (lane == 0) colsq_w[wid][k] = v;
    }
    __syncthreads();
    if (tid < 50) {
        float s = 0.f;
#pragma unroll
        for (int w = 0; w < 8; w++) s += colsq_w[w][tid];
        wcol[tid] = sqrtf(s);
    }
    if (tid < 3) {
        float s = 0.f;
#pragma unroll
        for (int w = 0; w < 8; w++) s += tn_w[w][tid];
        tnsq[tid] = s;
    }

    // ---- 2. kmix_v base verts, pred + gt (shared row loads) ----
    for (int l = tid; l < 600; l += 256) {
        int j = l / 3, c = l - 3 * j;
        int vid = (j < 68) ? keyindex[j] : ridx_v[j - 68];
        int r = 3 * vid + c;
        float uu = u[r];
        float s = uu, sg = uu;
        const float4* w4 = (const float4*)(w_shp + (size_t)r * 40);
#pragma unroll
        for (int q = 0; q < 10; q++) {
            float4 v = w4[q];
            s  += v.x * sp [12 + 4 * q] + v.y * sp [13 + 4 * q]
                + v.z * sp [14 + 4 * q] + v.w * sp [15 + 4 * q];
            sg += v.x * spg[12 + 4 * q] + v.y * spg[13 + 4 * q]
                + v.z * spg[14 + 4 * q] + v.w * spg[15 + 4 * q];
        }
        const float2* e2 = (const float2*)(w_exp + (size_t)r * 10);
#pragma unroll
        for (int q = 0; q < 5; q++) {
            float2 v = e2[q];
            s  += v.x * sp [52 + 2 * q] + v.y * sp [53 + 2 * q];
            sg += v.x * spg[52 + 2 * q] + v.y * spg[53 + 2 * q];
        }
        bv[l] = s; bvg[l] = sg;
    }
    __syncthreads();

    // ---- 3. weights + wpdc ----
    float wj = 0.f;
    if (tid < 62) {
        float pd = fabsf(sp[tid] - spg[tid]);
        if (tid < 11) {
            int cc = tid & 3;
            float sc = (cc < 3) ? sqrtf(tnsq[cc]) : 14.142135623730951f;  // sqrt(200)
            wj = pd * sc + 1e-6f;
        } else if (tid == 11) {
            wj = 1e-6f;
        } else {
            wj = 0.00057339936f * pd * wcol[tid - 12] + 1e-6f;
        }
    }
    red[tid] = wj;  // 0 for tid >= 62 (all real weights > 0)
    __syncthreads();
#pragma unroll
    for (int o = 128; o; o >>= 1) {
        if (tid < o) red[tid] = fmaxf(red[tid], red[tid + o]);
        __syncthreads();
    }
    float wmax = red[0];
    __syncthreads();

    float wpdc = 0.f;
    if (tid < 62 && tid != 11) {
        float d = input[n * 62 + tid] - target[n * 62 + tid];
        wpdc = (wj / wmax) * d * d;
    }

    // ---- 4. rotate kmix_v verts: vt = R*b + off (y-flip cancels in all uses) ----
    if (tid < 200) {
        float b0 = bv [3 * tid], b1 = bv [3 * tid + 1], b2 = bv [3 * tid + 2];
        float c0 = bvg[3 * tid], c1 = bvg[3 * tid + 1], c2 = bvg[3 * tid + 2];
#pragma unroll
        for (int i = 0; i < 3; i++) {
            vt [tid][i] = sp [4 * i] * b0 + sp [4 * i + 1] * b1 + sp [4 * i + 2] * b2 + sp [4 * i + 3];
            vtg[tid][i] = spg[4 * i] * c0 + spg[4 * i + 1] * c1 + spg[4 * i + 2] * c2 + spg[4 * i + 3];
        }
    }
    __syncthreads();

    // ---- 5. chamfer (200x200) + nwl (68 landmarks, normals column-sums) ----
    float cham = 0.f, nwl = 0.f;
    if (tid < 200) {
        float x0 = vtg[tid][0], x1 = vtg[tid][1], x2 = vtg[tid][2];  // gt point p=tid
        float y0 = vt [tid][0], y1 = vt [tid][1], y2 = vt [tid][2];  // pred point q=tid
        float m1 = 3.4e38f, m2 = 3.4e38f;
#pragma unroll 4
        for (int k = 0; k < 200; k++) {
            float a0 = x0 - vt[k][0], a1 = x1 - vt[k][1], a2 = x2 - vt[k][2];
            m1 = fminf(m1, a0 * a0 + a1 * a1 + a2 * a2);
            float b0 = vtg[k][0] - y0, b1 = vtg[k][1] - y1, b2 = vtg[k][2] - y2;
            m2 = fminf(m2, b0 * b0 + b1 * b1 + b2 * b2);
        }
        cham = m1 + m2;
    }
    if (tid < 68) {
        const float* nm = normals + (size_t)n * (68 * 68) + tid;
        float s = 0.f;
#pragma unroll 4
        for (int i = 0; i < 68; i++) s += nm[i * 68];
        float d0 = vtg[tid][0] - vt[tid][0];
        float d1 = vtg[tid][1] - vt[tid][1];
        float d2 = vtg[tid][2] - vt[tid][2];
        nwl = s * (d0 * d0 + d1 * d1 + d2 * d2);
    }

    // ---- 6. combine + deterministic block reduce ----
    const float k_wpdc = 1.f / (128.f * 62.f);
    const float k_vdc  = 3.f * 0.001f / (128.f * 200.f);
    const float k_nwl  = 3.f * 0.001f / (128.f * 68.f * 3.f);
    float tot = wpdc * k_wpdc + cham * k_vdc + nwl * k_nwl;
    red[tid] = tot;
    __syncthreads();
#pragma unroll
    for (int o = 128; o; o >>= 1) {
        if (tid < o) red[tid] += red[tid + o];
        __syncthreads();
    }
    if (tid == 0) g_partials[n] = red[0];
}

// Deterministic fixed-order final sum.
__global__ __launch_bounds__(128, 1)
void loss_finalize(float* __restrict__ out)
{
    __shared__ float s[128];
    int t = threadIdx.x;
    s[t] = g_partials[t];
    __syncthreads();
#pragma unroll
    for (int o = 64; o; o >>= 1) {
        if (t < o) s[t] += s[t + o];
        __syncthreads();
    }
    if (t == 0) out[0] = s[0];
}

extern "C" void kernel_launch(void* const* d_in, const int* in_sizes, int n_in,
                              void* d_out, int out_size)
{
    (void)in_sizes; (void)n_in; (void)out_size;
    loss_main<<<BATCH, 256>>>(
        (const float*)d_in[0],   // input
        (const float*)d_in[1],   // target
        (const float*)d_in[2],   // normals
        (const float*)d_in[3],   // param_mean
        (const float*)d_in[4],   // param_std
        (const float*)d_in[5],   // u
        (const float*)d_in[6],   // w_shp
        (const float*)d_in[7],   // w_exp
        (const int*)d_in[8],     // keyindex
        (const int*)d_in[9],     // resample_idx_w
        (const int*)d_in[10]);   // resample_idx_v
    loss_finalize<<<1, 128>>>((float*)d_out);
}